// round 2
// baseline (speedup 1.0000x reference)
#include <cuda_runtime.h>
#include <cstdint>

#define B_   8
#define HW_  16384

// ---------------- scratch ----------------
__device__ float g_Hp[B_*256*256];
__device__ float g_Mp[B_*256*256];
__device__ float g_Yh[B_*3*256*256];          // Qp,Kp,Vp per batch
__device__ float g_Ym[B_*2*256*256];          // Kmp,Vmp
__device__ float g_S [2*B_*256*256];          // scores/attn (h then m)
__device__ float g_ZT[B_*512*256];            // [b][d(512)][p]: Zh rows 0..255, Zm 256..511
__device__ float g_G [B_*768*256];            // Wzz @ Zcat on 16x16 grid
__device__ float g_Wzz[768*512];
__device__ float g_bf[768];
__device__ float g_cmb[(size_t)B_*768*HW_];   // 384 MiB

// ---------------- pooling ----------------
__global__ void pool_kernel(const float* __restrict__ h, const float* __restrict__ m)
{
    int gwarp = (blockIdx.x * blockDim.x + threadIdx.x) >> 5;
    int lane  = threadIdx.x & 31;
    const float* src = blockIdx.y ? m : h;
    float* dst       = blockIdx.y ? g_Mp : g_Hp;
    float2 v = *(const float2*)(src + (size_t)gwarp * 64 + lane * 2);
    float s = v.x + v.y;
    #pragma unroll
    for (int o = 16; o; o >>= 1) s += __shfl_xor_sync(0xffffffffu, s, o);
    if (lane == 0) dst[gwarp] = s * (1.0f / 64.0f);
}

// ---------------- generic fp32 GEMM (64x64 tile, 256 thr) ----------------
template<bool TA, bool TB, bool BIAS>
__global__ void __launch_bounds__(256) gemm_f32(
    const float* __restrict__ A, int lda, long long sA,
    const float* __restrict__ B, int ldb, long long sB,
    float* __restrict__ C, int ldc, long long sC,
    const float* __restrict__ bias, int K)
{
    __shared__ float As[16][68];   // [k][m]
    __shared__ float Bs[16][68];   // [k][n]
    int tid = threadIdx.x;
    const float* Ab = A + (long long)blockIdx.z * sA;
    const float* Bb = B + (long long)blockIdx.z * sB;
    float* Cb       = C + (long long)blockIdx.z * sC;
    int m0 = blockIdx.y * 64, n0 = blockIdx.x * 64;
    float acc[4][4] = {};
    int tr = tid >> 4, tc = tid & 15;

    for (int k0 = 0; k0 < K; k0 += 16) {
        if (!TA) {
            int mm = tid >> 2, kq = (tid & 3) * 4;
            float4 v = *(const float4*)&Ab[(size_t)(m0+mm)*lda + k0 + kq];
            As[kq+0][mm]=v.x; As[kq+1][mm]=v.y; As[kq+2][mm]=v.z; As[kq+3][mm]=v.w;
        } else {
            int kk = tid >> 4, mq = (tid & 15) * 4;
            float4 v = *(const float4*)&Ab[(size_t)(k0+kk)*lda + m0 + mq];
            As[kk][mq+0]=v.x; As[kk][mq+1]=v.y; As[kk][mq+2]=v.z; As[kk][mq+3]=v.w;
        }
        if (!TB) {
            int kk = tid >> 4, nq = (tid & 15) * 4;
            float4 v = *(const float4*)&Bb[(size_t)(k0+kk)*ldb + n0 + nq];
            Bs[kk][nq+0]=v.x; Bs[kk][nq+1]=v.y; Bs[kk][nq+2]=v.z; Bs[kk][nq+3]=v.w;
        } else {
            int nn = tid >> 2, kq = (tid & 3) * 4;
            float4 v = *(const float4*)&Bb[(size_t)(n0+nn)*ldb + k0 + kq];
            Bs[kq+0][nn]=v.x; Bs[kq+1][nn]=v.y; Bs[kq+2][nn]=v.z; Bs[kq+3][nn]=v.w;
        }
        __syncthreads();
        #pragma unroll
        for (int k = 0; k < 16; k++) {
            float4 a4 = *(const float4*)&As[k][tr*4];
            float4 b4 = *(const float4*)&Bs[k][tc*4];
            float a[4] = {a4.x,a4.y,a4.z,a4.w};
            float b[4] = {b4.x,b4.y,b4.z,b4.w};
            #pragma unroll
            for (int i = 0; i < 4; i++)
                #pragma unroll
                for (int j = 0; j < 4; j++) acc[i][j] += a[i] * b[j];
        }
        __syncthreads();
    }
    #pragma unroll
    for (int i = 0; i < 4; i++) {
        float bv = BIAS ? bias[m0 + tr*4 + i] : 0.0f;
        float4 v = { acc[i][0]+bv, acc[i][1]+bv, acc[i][2]+bv, acc[i][3]+bv };
        *(float4*)&Cb[(size_t)(m0+tr*4+i)*ldc + n0 + tc*4] = v;
    }
}

// ---------------- softmax over rows of 256 ----------------
__global__ void softmax_kernel()
{
    float* row = g_S + (size_t)blockIdx.x * 256;
    int tid = threadIdx.x;
    float v = row[tid];
    __shared__ float red[8];
    float mx = v;
    #pragma unroll
    for (int o = 16; o; o >>= 1) mx = fmaxf(mx, __shfl_xor_sync(0xffffffffu, mx, o));
    if ((tid & 31) == 0) red[tid >> 5] = mx;
    __syncthreads();
    float bmax = red[0];
    #pragma unroll
    for (int i = 1; i < 8; i++) bmax = fmaxf(bmax, red[i]);
    float e = expf(v - bmax);
    float s = e;
    #pragma unroll
    for (int o = 16; o; o >>= 1) s += __shfl_xor_sync(0xffffffffu, s, o);
    __syncthreads();
    if ((tid & 31) == 0) red[tid >> 5] = s;
    __syncthreads();
    float bsum = red[0];
    #pragma unroll
    for (int i = 1; i < 8; i++) bsum += red[i];
    row[tid] = e / bsum;
}

// ---------------- bfold[r] = bm[r] + sum_{o<512} wm[r,o]*bz[o] ----------
__global__ void bfold_kernel(const float* __restrict__ wm,
                             const float* __restrict__ bz,
                             const float* __restrict__ bm)
{
    int r = blockIdx.x * blockDim.x + threadIdx.x;
    if (r < 768) {
        float s = bm[r];
        for (int o = 0; o < 512; o++) s += wm[(size_t)r*768 + o] * bz[o];
        g_bf[r] = s;
    }
}

// ---------------- big tf32 GEMM: cmb[b] = Wh @ h[b] + bfold -------------
__device__ __forceinline__ uint32_t f2tf(float f) {
    uint32_t u; asm("cvt.rna.tf32.f32 %0, %1;" : "=r"(u) : "f"(f)); return u;
}

__global__ void __launch_bounds__(256) big_gemm(
    const float* __restrict__ W, int lda,
    const float* __restrict__ X,
    const float* __restrict__ bias,
    float* __restrict__ C)
{
    __shared__ uint32_t As[32 * 136];   // [k][m] pad 8
    __shared__ uint32_t Bs[32 * 136];   // [k][n]
    int tid = threadIdx.x;
    int m0 = blockIdx.y * 128, n0 = blockIdx.x * 128;
    const float* Xb = X + (size_t)blockIdx.z * 256 * 16384;
    float* Cb       = C + (size_t)blockIdx.z * 768 * 16384;
    int lane = tid & 31, wid = tid >> 5;
    int wmi = wid >> 2, wni = wid & 3;
    int g = lane >> 2, tg = lane & 3;

    float acc[4][4][4] = {};

    int ar  = tid >> 1;
    int akq = (tid & 1) * 16;
    int bk  = tid >> 3;
    int bf0 = tid & 7;

    float4 pa[4], pb[4];
    #pragma unroll
    for (int i = 0; i < 4; i++)
        pa[i] = *(const float4*)(W + (size_t)(m0+ar)*lda + akq + i*4);
    #pragma unroll
    for (int i = 0; i < 4; i++)
        pb[i] = *(const float4*)(Xb + (size_t)bk*16384 + n0 + (bf0 + i*8)*4);

    for (int kt = 0; kt < 8; kt++) {
        #pragma unroll
        for (int i = 0; i < 4; i++) {
            int k = akq + i*4;
            As[(k+0)*136 + ar] = f2tf(pa[i].x);
            As[(k+1)*136 + ar] = f2tf(pa[i].y);
            As[(k+2)*136 + ar] = f2tf(pa[i].z);
            As[(k+3)*136 + ar] = f2tf(pa[i].w);
        }
        #pragma unroll
        for (int i = 0; i < 4; i++) {
            uint4 w4 = { f2tf(pb[i].x), f2tf(pb[i].y), f2tf(pb[i].z), f2tf(pb[i].w) };
            *(uint4*)&Bs[bk*136 + (bf0 + i*8)*4] = w4;
        }
        __syncthreads();
        if (kt < 7) {
            int k0 = (kt + 1) * 32;
            #pragma unroll
            for (int i = 0; i < 4; i++)
                pa[i] = *(const float4*)(W + (size_t)(m0+ar)*lda + k0 + akq + i*4);
            #pragma unroll
            for (int i = 0; i < 4; i++)
                pb[i] = *(const float4*)(Xb + (size_t)(k0+bk)*16384 + n0 + (bf0 + i*8)*4);
        }
        #pragma unroll
        for (int ks = 0; ks < 4; ks++) {
            int kk = ks * 8;
            uint32_t af[4][4], bfr[4][2];
            #pragma unroll
            for (int mt = 0; mt < 4; mt++) {
                int mloc = wmi*64 + mt*16;
                af[mt][0] = As[(kk+tg  )*136 + mloc + g    ];
                af[mt][1] = As[(kk+tg  )*136 + mloc + 8 + g];
                af[mt][2] = As[(kk+tg+4)*136 + mloc + g    ];
                af[mt][3] = As[(kk+tg+4)*136 + mloc + 8 + g];
            }
            #pragma unroll
            for (int nt = 0; nt < 4; nt++) {
                int nloc = wni*32 + nt*8;
                bfr[nt][0] = Bs[(kk+tg  )*136 + nloc + g];
                bfr[nt][1] = Bs[(kk+tg+4)*136 + nloc + g];
            }
            #pragma unroll
            for (int mt = 0; mt < 4; mt++)
                #pragma unroll
                for (int nt = 0; nt < 4; nt++)
                    asm volatile(
                        "mma.sync.aligned.m16n8k8.row.col.f32.tf32.tf32.f32 "
                        "{%0,%1,%2,%3},{%4,%5,%6,%7},{%8,%9},{%0,%1,%2,%3};\n"
                        : "+f"(acc[mt][nt][0]), "+f"(acc[mt][nt][1]),
                          "+f"(acc[mt][nt][2]), "+f"(acc[mt][nt][3])
                        : "r"(af[mt][0]), "r"(af[mt][1]), "r"(af[mt][2]), "r"(af[mt][3]),
                          "r"(bfr[nt][0]), "r"(bfr[nt][1]));
        }
        __syncthreads();
    }
    #pragma unroll
    for (int mt = 0; mt < 4; mt++) {
        int r0 = m0 + wmi*64 + mt*16 + g;
        float b0 = bias[r0], b1 = bias[r0 + 8];
        #pragma unroll
        for (int nt = 0; nt < 4; nt++) {
            int col = n0 + wni*32 + nt*8 + tg*2;
            float2 v0 = { acc[mt][nt][0] + b0, acc[mt][nt][1] + b0 };
            float2 v1 = { acc[mt][nt][2] + b1, acc[mt][nt][3] + b1 };
            *(float2*)&Cb[(size_t)r0*16384 + col]     = v0;
            *(float2*)&Cb[(size_t)(r0+8)*16384 + col] = v1;
        }
    }
}

// ---------------- gating + bilinear upsample of G ----------------
__global__ void gating_kernel(const float* __restrict__ m_in, float* __restrict__ out)
{
    int x = threadIdx.x;     // 0..127
    int y = blockIdx.x;      // 0..127
    int o = blockIdx.y;      // 0..255
    int b = blockIdx.z;
    __shared__ float gy[3][16];

    float sy = (y + 0.5f) * 0.125f - 0.5f; if (sy < 0.0f) sy = 0.0f;
    int y0 = (int)sy; float fy = sy - (float)y0; int y1 = min(y0 + 1, 15);
    if (x < 48) {
        int c = x >> 4, px = x & 15;
        const float* Gb = g_G + ((size_t)b*768 + o + c*256) * 256;
        gy[c][px] = (1.0f - fy) * Gb[y0*16 + px] + fy * Gb[y1*16 + px];
    }
    __syncthreads();

    float sx = (x + 0.5f) * 0.125f - 0.5f; if (sx < 0.0f) sx = 0.0f;
    int x0 = (int)sx; float fx = sx - (float)x0; int x1 = min(x0 + 1, 15);
    float g0 = (1.0f - fx) * gy[0][x0] + fx * gy[0][x1];
    float g1 = (1.0f - fx) * gy[1][x0] + fx * gy[1][x1];
    float g2 = (1.0f - fx) * gy[2][x0] + fx * gy[2][x1];

    size_t pix   = (size_t)y * 128 + x;
    size_t cbase = ((size_t)b*768 + o) * 16384 + pix;
    float mo = g_cmb[cbase]                       + g0;
    float mg = g_cmb[cbase + (size_t)256*16384]   + g1;
    float mi = g_cmb[cbase + (size_t)512*16384]   + g2;
    float mval = m_in[((size_t)b*256 + o) * 16384 + pix];

    float gi = 1.0f / (1.0f + expf(-mi));
    float nm = (1.0f - gi) * mval + gi * tanhf(mg);
    float nh = nm / (1.0f + expf(-mo));

    size_t oidx = ((size_t)b*256 + o) * 16384 + pix;
    out[oidx] = nh;                                    // new_h
    out[(size_t)B_*256*16384 + oidx] = nm;             // new_m
}

// ---------------- launcher ----------------
extern "C" void kernel_launch(void* const* d_in, const int* in_sizes, int n_in,
                              void* d_out, int out_size)
{
    const float* h   = (const float*)d_in[0];
    const float* m   = (const float*)d_in[1];
    const float* wq  = (const float*)d_in[2];
    const float* bq  = (const float*)d_in[3];
    const float* wk  = (const float*)d_in[4];
    const float* bk  = (const float*)d_in[5];
    const float* wv  = (const float*)d_in[6];
    const float* bv  = (const float*)d_in[7];
    const float* wkm = (const float*)d_in[8];
    const float* bkm = (const float*)d_in[9];
    const float* wvm = (const float*)d_in[10];
    const float* bvm = (const float*)d_in[11];
    const float* wz  = (const float*)d_in[12];
    const float* bz  = (const float*)d_in[13];
    const float* wm  = (const float*)d_in[14];
    const float* bm  = (const float*)d_in[15];
    float* out = (float*)d_out;

    float *Hp, *Mp, *Yh, *Ym, *S, *ZT, *G, *Wzz, *bf, *cmb;
    cudaGetSymbolAddress((void**)&Hp,  g_Hp);
    cudaGetSymbolAddress((void**)&Mp,  g_Mp);
    cudaGetSymbolAddress((void**)&Yh,  g_Yh);
    cudaGetSymbolAddress((void**)&Ym,  g_Ym);
    cudaGetSymbolAddress((void**)&S,   g_S);
    cudaGetSymbolAddress((void**)&ZT,  g_ZT);
    cudaGetSymbolAddress((void**)&G,   g_G);
    cudaGetSymbolAddress((void**)&Wzz, g_Wzz);
    cudaGetSymbolAddress((void**)&bf,  g_bf);
    cudaGetSymbolAddress((void**)&cmb, g_cmb);

    const long long PB = 256*256;        // per-batch pooled slab

    // 1) pooling
    pool_kernel<<<dim3(65536, 2), 256>>>(h, m);

    // 2) folded weights / bias
    gemm_f32<false,false,false><<<dim3(8, 12, 1), 256>>>(
        wm, 768, 0, wz, 512, 0, Wzz, 512, 0, nullptr, 512);
    bfold_kernel<<<3, 256>>>(wm, bz, bm);

    // 3) projections (C[d,p] = W @ pooled + bias)
    gemm_f32<false,false,true><<<dim3(4,4,8), 256>>>(wq, 256, 0, Hp, 256, PB, Yh + 0*PB, 256, 3*PB, bq, 256);
    gemm_f32<false,false,true><<<dim3(4,4,8), 256>>>(wk, 256, 0, Hp, 256, PB, Yh + 1*PB, 256, 3*PB, bk, 256);
    gemm_f32<false,false,true><<<dim3(4,4,8), 256>>>(wv, 256, 0, Hp, 256, PB, Yh + 2*PB, 256, 3*PB, bv, 256);
    gemm_f32<false,false,true><<<dim3(4,4,8), 256>>>(wkm,256, 0, Mp, 256, PB, Ym + 0*PB, 256, 2*PB, bkm, 256);
    gemm_f32<false,false,true><<<dim3(4,4,8), 256>>>(wvm,256, 0, Mp, 256, PB, Ym + 1*PB, 256, 2*PB, bvm, 256);

    // 4) scores S[p,q] = Qp^T @ K
    gemm_f32<true,false,false><<<dim3(4,4,8), 256>>>(Yh + 0*PB, 256, 3*PB, Yh + 1*PB, 256, 3*PB, S,          256, PB, nullptr, 256);
    gemm_f32<true,false,false><<<dim3(4,4,8), 256>>>(Yh + 0*PB, 256, 3*PB, Ym + 0*PB, 256, 2*PB, S + 8*PB,   256, PB, nullptr, 256);

    // 5) softmax (rows of 256)
    softmax_kernel<<<4096, 256>>>();

    // 6) ZT[d,p] = V @ A^T
    gemm_f32<false,true,false><<<dim3(4,4,8), 256>>>(Yh + 2*PB, 256, 3*PB, S,        256, PB, ZT,        256, 2*PB, nullptr, 256);
    gemm_f32<false,true,false><<<dim3(4,4,8), 256>>>(Ym + 1*PB, 256, 2*PB, S + 8*PB, 256, PB, ZT + PB,   256, 2*PB, nullptr, 256);

    // 7) G = Wzz @ ZTcat  (small 16x16 grid)
    gemm_f32<false,false,false><<<dim3(4,12,8), 256>>>(Wzz, 512, 0, ZT, 256, 2*PB, G, 256, 768LL*256, nullptr, 512);

    // 8) big GEMM: Wh @ h + bfold
    big_gemm<<<dim3(128, 6, 8), 256>>>(wm + 512, 768, h, bf, cmb);

    // 9) gating + upsample + outputs
    gating_kernel<<<dim3(128, 256, 8), 128>>>(m, out);
}

// round 3
// speedup vs baseline: 1.0514x; 1.0514x over previous
#include <cuda_runtime.h>
#include <cstdint>

#define B_   8
#define HW_  16384
#define PB   (256LL*256LL)

// ---------------- scratch ----------------
__device__ float g_Hp[B_*256*256];
__device__ float g_Mp[B_*256*256];
__device__ float g_Yh[B_*3*256*256];          // Qp,Kp,Vp per batch
__device__ float g_Ym[B_*2*256*256];          // Kmp,Vmp
__device__ float g_S [2*B_*256*256];          // scores/attn (h then m)
__device__ float g_ZT[B_*512*256];            // Zh rows 0..255, Zm 256..511 (d-major)
__device__ float g_G [B_*768*256];            // Wzz @ Zcat on 16x16 grid
__device__ float g_Wzz[768*512];
__device__ float g_bf[768];

// ---------------- pooling ----------------
__global__ void pool_kernel(const float* __restrict__ h, const float* __restrict__ m)
{
    int gwarp = (blockIdx.x * blockDim.x + threadIdx.x) >> 5;
    int lane  = threadIdx.x & 31;
    const float* src = blockIdx.y ? m : h;
    float* dst       = blockIdx.y ? g_Mp : g_Hp;
    float2 v = *(const float2*)(src + (size_t)gwarp * 64 + lane * 2);
    float s = v.x + v.y;
    #pragma unroll
    for (int o = 16; o; o >>= 1) s += __shfl_xor_sync(0xffffffffu, s, o);
    if (lane == 0) dst[gwarp] = s * (1.0f / 64.0f);
}

// ---------------- batched-pointer fp32 GEMM (64x64 tile) ----------------
struct GArgs {
    const float* A[40];
    const float* B[40];
    float*       C[40];
    const float* bias[40];
};

template<bool TA, bool TB, bool BIAS>
__global__ void __launch_bounds__(256) gemm_b(
    GArgs ga, int lda, int ldb, int ldc, int K)
{
    __shared__ float As[16][68];   // [k][m]
    __shared__ float Bs[16][68];   // [k][n]
    int tid = threadIdx.x;
    int z = blockIdx.z;
    const float* Ab = ga.A[z];
    const float* Bb = ga.B[z];
    float* Cb       = ga.C[z];
    int m0 = blockIdx.y * 64, n0 = blockIdx.x * 64;
    float acc[4][4] = {};
    int tr = tid >> 4, tc = tid & 15;

    for (int k0 = 0; k0 < K; k0 += 16) {
        if (!TA) {
            int mm = tid >> 2, kq = (tid & 3) * 4;
            float4 v = *(const float4*)&Ab[(size_t)(m0+mm)*lda + k0 + kq];
            As[kq+0][mm]=v.x; As[kq+1][mm]=v.y; As[kq+2][mm]=v.z; As[kq+3][mm]=v.w;
        } else {
            int kk = tid >> 4, mq = (tid & 15) * 4;
            float4 v = *(const float4*)&Ab[(size_t)(k0+kk)*lda + m0 + mq];
            As[kk][mq+0]=v.x; As[kk][mq+1]=v.y; As[kk][mq+2]=v.z; As[kk][mq+3]=v.w;
        }
        if (!TB) {
            int kk = tid >> 4, nq = (tid & 15) * 4;
            float4 v = *(const float4*)&Bb[(size_t)(k0+kk)*ldb + n0 + nq];
            Bs[kk][nq+0]=v.x; Bs[kk][nq+1]=v.y; Bs[kk][nq+2]=v.z; Bs[kk][nq+3]=v.w;
        } else {
            int nn = tid >> 2, kq = (tid & 3) * 4;
            float4 v = *(const float4*)&Bb[(size_t)(n0+nn)*ldb + k0 + kq];
            Bs[kq+0][nn]=v.x; Bs[kq+1][nn]=v.y; Bs[kq+2][nn]=v.z; Bs[kq+3][nn]=v.w;
        }
        __syncthreads();
        #pragma unroll
        for (int k = 0; k < 16; k++) {
            float4 a4 = *(const float4*)&As[k][tr*4];
            float4 b4 = *(const float4*)&Bs[k][tc*4];
            float a[4] = {a4.x,a4.y,a4.z,a4.w};
            float b[4] = {b4.x,b4.y,b4.z,b4.w};
            #pragma unroll
            for (int i = 0; i < 4; i++)
                #pragma unroll
                for (int j = 0; j < 4; j++) acc[i][j] += a[i] * b[j];
        }
        __syncthreads();
    }
    #pragma unroll
    for (int i = 0; i < 4; i++) {
        float bv = BIAS ? ga.bias[z][m0 + tr*4 + i] : 0.0f;
        float4 v = { acc[i][0]+bv, acc[i][1]+bv, acc[i][2]+bv, acc[i][3]+bv };
        *(float4*)&Cb[(size_t)(m0+tr*4+i)*ldc + n0 + tc*4] = v;
    }
}

// ---------------- softmax over rows of 256 ----------------
__global__ void softmax_kernel()
{
    float* row = g_S + (size_t)blockIdx.x * 256;
    int tid = threadIdx.x;
    float v = row[tid];
    __shared__ float red[8];
    float mx = v;
    #pragma unroll
    for (int o = 16; o; o >>= 1) mx = fmaxf(mx, __shfl_xor_sync(0xffffffffu, mx, o));
    if ((tid & 31) == 0) red[tid >> 5] = mx;
    __syncthreads();
    float bmax = red[0];
    #pragma unroll
    for (int i = 1; i < 8; i++) bmax = fmaxf(bmax, red[i]);
    float e = expf(v - bmax);
    float s = e;
    #pragma unroll
    for (int o = 16; o; o >>= 1) s += __shfl_xor_sync(0xffffffffu, s, o);
    __syncthreads();
    if ((tid & 31) == 0) red[tid >> 5] = s;
    __syncthreads();
    float bsum = red[0];
    #pragma unroll
    for (int i = 1; i < 8; i++) bsum += red[i];
    row[tid] = e / bsum;
}

// ---------------- bfold[r] = bm[r] + sum_{o<512} wm[r,o]*bz[o] ----------
__global__ void bfold_kernel(const float* __restrict__ wm,
                             const float* __restrict__ bz,
                             const float* __restrict__ bm)
{
    int r = blockIdx.x * blockDim.x + threadIdx.x;
    if (r < 768) {
        float s = bm[r];
        for (int o = 0; o < 512; o++) s += wm[(size_t)r*768 + o] * bz[o];
        g_bf[r] = s;
    }
}

// ---------------- fused big GEMM + bilinear G + gating -------------------
// Block: 64 o-channels x 128 pixels (one image row y). Computes mo/mg/mi
// (3 wm slabs, M=192 rows) over K=256, then gates and writes new_h/new_m.
__device__ __forceinline__ uint32_t f2tf(float f) {
    uint32_t u; asm("cvt.rna.tf32.f32 %0, %1;" : "=r"(u) : "f"(f)); return u;
}

__global__ void __launch_bounds__(256) fused_gemm_gate(
    const float* __restrict__ wm,     // [768,768]; X-part cols 512..767
    const float* __restrict__ h,
    const float* __restrict__ m_in,
    float* __restrict__ out)
{
    __shared__ uint32_t As[192 * 36];   // tf32, row-major [r][k], pad 36
    __shared__ uint32_t Bs[32 * 136];   // tf32, [k][n], pad 136
    int tid = threadIdx.x;
    int y  = blockIdx.x;                // image row 0..127
    int m0 = blockIdx.y * 64;           // o base
    int b  = blockIdx.z;
    int lane = tid & 31, wid = tid >> 5;
    int wmi = wid >> 1;                 // 0..3 : 16 o's each
    int wni = wid & 1;                  // 0..1 : 64 px each
    int g = lane >> 2, tg = lane & 3;

    const float* Xb = h + (size_t)b * 256 * HW_ + (size_t)y * 128;

    float acc[3][8][4];
    #pragma unroll
    for (int s = 0; s < 3; s++)
        #pragma unroll
        for (int n = 0; n < 8; n++)
            #pragma unroll
            for (int c = 0; c < 4; c++) acc[s][n][c] = 0.0f;

    // A: 192 rows x 32k = 1536 float4; 6/thread. r=idx>>3, kq=(idx&7)*4
    // B: 32 k x 128 = 1024 float4; 4/thread. kk=idx>>5, nf=idx&31
    float4 pa[6], pb[4];
    #pragma unroll
    for (int i = 0; i < 6; i++) {
        int idx = tid + 256*i;
        int r = idx >> 3, kq = (idx & 7) * 4;
        int grow = (r >> 6) * 256 + m0 + (r & 63);
        pa[i] = *(const float4*)&wm[(size_t)grow*768 + 512 + kq];
    }
    #pragma unroll
    for (int i = 0; i < 4; i++) {
        int idx = tid + 256*i;
        int kk = idx >> 5, nf = idx & 31;
        pb[i] = *(const float4*)&Xb[(size_t)kk*HW_ + nf*4];
    }

    for (int kt = 0; kt < 8; kt++) {
        #pragma unroll
        for (int i = 0; i < 6; i++) {
            int idx = tid + 256*i;
            int r = idx >> 3, kq = (idx & 7) * 4;
            uint4 t = { f2tf(pa[i].x), f2tf(pa[i].y), f2tf(pa[i].z), f2tf(pa[i].w) };
            *(uint4*)&As[r*36 + kq] = t;
        }
        #pragma unroll
        for (int i = 0; i < 4; i++) {
            int idx = tid + 256*i;
            int kk = idx >> 5, nf = idx & 31;
            uint4 t = { f2tf(pb[i].x), f2tf(pb[i].y), f2tf(pb[i].z), f2tf(pb[i].w) };
            *(uint4*)&Bs[kk*136 + nf*4] = t;
        }
        __syncthreads();
        if (kt < 7) {
            int k0 = (kt + 1) * 32;
            #pragma unroll
            for (int i = 0; i < 6; i++) {
                int idx = tid + 256*i;
                int r = idx >> 3, kq = (idx & 7) * 4;
                int grow = (r >> 6) * 256 + m0 + (r & 63);
                pa[i] = *(const float4*)&wm[(size_t)grow*768 + 512 + k0 + kq];
            }
            #pragma unroll
            for (int i = 0; i < 4; i++) {
                int idx = tid + 256*i;
                int kk = idx >> 5, nf = idx & 31;
                pb[i] = *(const float4*)&Xb[(size_t)(k0+kk)*HW_ + nf*4];
            }
        }
        #pragma unroll
        for (int ks = 0; ks < 4; ks++) {
            int kk = ks * 8;
            uint32_t bfr[8][2];
            #pragma unroll
            for (int nt = 0; nt < 8; nt++) {
                int n = wni*64 + nt*8;
                bfr[nt][0] = Bs[(kk+tg  )*136 + n + g];
                bfr[nt][1] = Bs[(kk+tg+4)*136 + n + g];
            }
            #pragma unroll
            for (int s = 0; s < 3; s++) {
                int rb = s*64 + wmi*16;
                uint32_t a0 = As[(rb + g    )*36 + kk + tg    ];
                uint32_t a1 = As[(rb + 8 + g)*36 + kk + tg    ];
                uint32_t a2 = As[(rb + g    )*36 + kk + tg + 4];
                uint32_t a3 = As[(rb + 8 + g)*36 + kk + tg + 4];
                #pragma unroll
                for (int nt = 0; nt < 8; nt++)
                    asm volatile(
                        "mma.sync.aligned.m16n8k8.row.col.f32.tf32.tf32.f32 "
                        "{%0,%1,%2,%3},{%4,%5,%6,%7},{%8,%9},{%0,%1,%2,%3};\n"
                        : "+f"(acc[s][nt][0]), "+f"(acc[s][nt][1]),
                          "+f"(acc[s][nt][2]), "+f"(acc[s][nt][3])
                        : "r"(a0), "r"(a1), "r"(a2), "r"(a3),
                          "r"(bfr[nt][0]), "r"(bfr[nt][1]));
            }
        }
        __syncthreads();
    }

    // ---- epilogue: gy = y-interpolated G rows, then x-interp + gating ----
    float* gy = (float*)As;   // [192][16], reuse As
    float sy = (y + 0.5f) * 0.125f - 0.5f; if (sy < 0.0f) sy = 0.0f;
    int y0 = (int)sy; float fy = sy - (float)y0; int y1 = min(y0 + 1, 15);
    #pragma unroll
    for (int i = 0; i < 12; i++) {
        int idx = tid + 256*i;
        int r = idx >> 4, px = idx & 15;
        int grow = (r >> 6) * 256 + m0 + (r & 63);
        const float* Gb = g_G + ((size_t)b*768 + grow) * 256;
        gy[r*16 + px] = (1.0f - fy) * Gb[y0*16 + px] + fy * Gb[y1*16 + px];
    }
    __syncthreads();

    #pragma unroll
    for (int rr = 0; rr < 2; rr++) {
        int o_loc  = wmi*16 + g + rr*8;
        int o_glob = m0 + o_loc;
        float bv0 = g_bf[o_glob];
        float bv1 = g_bf[256 + o_glob];
        float bv2 = g_bf[512 + o_glob];
        const float* mrow = m_in + ((size_t)b*256 + o_glob)*HW_ + (size_t)y*128;
        float* hrow = out + ((size_t)b*256 + o_glob)*HW_ + (size_t)y*128;
        float* mrow_out = hrow + (size_t)B_*256*HW_;
        #pragma unroll
        for (int nt = 0; nt < 8; nt++) {
            int x = wni*64 + nt*8 + tg*2;
            float2 mv = *(const float2*)&mrow[x];
            float nh[2], nm[2];
            #pragma unroll
            for (int px = 0; px < 2; px++) {
                int xx = x + px;
                float sx = (xx + 0.5f) * 0.125f - 0.5f; if (sx < 0.0f) sx = 0.0f;
                int x0 = (int)sx; float fx = sx - (float)x0; int x1 = min(x0 + 1, 15);
                float g0 = (1.0f-fx)*gy[(0*64+o_loc)*16 + x0] + fx*gy[(0*64+o_loc)*16 + x1];
                float g1 = (1.0f-fx)*gy[(1*64+o_loc)*16 + x0] + fx*gy[(1*64+o_loc)*16 + x1];
                float g2 = (1.0f-fx)*gy[(2*64+o_loc)*16 + x0] + fx*gy[(2*64+o_loc)*16 + x1];
                int c = rr*2 + px;
                float mo = acc[0][nt][c] + bv0 + g0;
                float mg = acc[1][nt][c] + bv1 + g1;
                float mi = acc[2][nt][c] + bv2 + g2;
                float mval = px ? mv.y : mv.x;
                float gi = 1.0f / (1.0f + expf(-mi));
                float nmv = (1.0f - gi) * mval + gi * tanhf(mg);
                nm[px] = nmv;
                nh[px] = nmv / (1.0f + expf(-mo));
            }
            *(float2*)&hrow[x]     = make_float2(nh[0], nh[1]);
            *(float2*)&mrow_out[x] = make_float2(nm[0], nm[1]);
        }
    }
}

// ---------------- launcher ----------------
extern "C" void kernel_launch(void* const* d_in, const int* in_sizes, int n_in,
                              void* d_out, int out_size)
{
    const float* h   = (const float*)d_in[0];
    const float* m   = (const float*)d_in[1];
    const float* wq  = (const float*)d_in[2];
    const float* bq  = (const float*)d_in[3];
    const float* wk  = (const float*)d_in[4];
    const float* bk  = (const float*)d_in[5];
    const float* wv  = (const float*)d_in[6];
    const float* bv  = (const float*)d_in[7];
    const float* wkm = (const float*)d_in[8];
    const float* bkm = (const float*)d_in[9];
    const float* wvm = (const float*)d_in[10];
    const float* bvm = (const float*)d_in[11];
    const float* wz  = (const float*)d_in[12];
    const float* bz  = (const float*)d_in[13];
    const float* wm  = (const float*)d_in[14];
    const float* bm  = (const float*)d_in[15];
    float* out = (float*)d_out;

    float *Hp, *Mp, *Yh, *Ym, *S, *ZT, *G, *Wzz;
    cudaGetSymbolAddress((void**)&Hp,  g_Hp);
    cudaGetSymbolAddress((void**)&Mp,  g_Mp);
    cudaGetSymbolAddress((void**)&Yh,  g_Yh);
    cudaGetSymbolAddress((void**)&Ym,  g_Ym);
    cudaGetSymbolAddress((void**)&S,   g_S);
    cudaGetSymbolAddress((void**)&ZT,  g_ZT);
    cudaGetSymbolAddress((void**)&G,   g_G);
    cudaGetSymbolAddress((void**)&Wzz, g_Wzz);

    // 1) pooling
    pool_kernel<<<dim3(65536, 2), 256>>>(h, m);

    // 2) folded weights / bias (independent of pooling)
    {
        GArgs ga = {};
        ga.A[0] = wm; ga.B[0] = wz; ga.C[0] = Wzz;
        gemm_b<false,false,false><<<dim3(8,12,1), 256>>>(ga, 768, 512, 512, 512);
    }
    bfold_kernel<<<3, 256>>>(wm, bz, bm);

    // 3) all five projections in one launch (z = slab*8 + batch)
    {
        GArgs ga = {};
        const float* W5[5] = { wq, wk, wv, wkm, wvm };
        const float* b5[5] = { bq, bk, bv, bkm, bvm };
        for (int s = 0; s < 5; s++)
            for (int bt = 0; bt < 8; bt++) {
                int z = s*8 + bt;
                ga.A[z] = W5[s];
                ga.B[z] = (s < 3 ? Hp : Mp) + bt*PB;
                ga.C[z] = (s < 3) ? Yh + bt*3*PB + s*PB
                                  : Ym + bt*2*PB + (s-3)*PB;
                ga.bias[z] = b5[s];
            }
        gemm_b<false,false,true><<<dim3(4,4,40), 256>>>(ga, 256, 256, 256, 256);
    }

    // 4) scores (h and m) in one launch: S[z][p,q] = Q^T K
    {
        GArgs ga = {};
        for (int z = 0; z < 16; z++) {
            int bt = z & 7;
            ga.A[z] = Yh + bt*3*PB;                                   // Qp
            ga.B[z] = (z < 8) ? Yh + bt*3*PB + PB : Ym + bt*2*PB;     // Kp / Kmp
            ga.C[z] = S + (long long)z*PB;
        }
        gemm_b<true,false,false><<<dim3(4,4,16), 256>>>(ga, 256, 256, 256, 256);
    }

    // 5) softmax
    softmax_kernel<<<4096, 256>>>();

    // 6) ZT[d,p] = V @ A^T (h and m) in one launch
    {
        GArgs ga = {};
        for (int z = 0; z < 16; z++) {
            int bt = z & 7;
            ga.A[z] = (z < 8) ? Yh + bt*3*PB + 2*PB : Ym + bt*2*PB + PB;
            ga.B[z] = S + (long long)z*PB;
            ga.C[z] = ZT + bt*2*PB + ((z < 8) ? 0 : PB);
        }
        gemm_b<false,true,false><<<dim3(4,4,16), 256>>>(ga, 256, 256, 256, 256);
    }

    // 7) G = Wzz @ ZTcat
    {
        GArgs ga = {};
        for (int bt = 0; bt < 8; bt++) {
            ga.A[bt] = Wzz;
            ga.B[bt] = ZT + bt*2*PB;
            ga.C[bt] = G + (long long)bt*768*256;
        }
        gemm_b<false,false,false><<<dim3(4,12,8), 256>>>(ga, 512, 256, 256, 512);
    }

    // 8) fused big GEMM + upsample + gating -> outputs
    fused_gemm_gate<<<dim3(128, 4, 8), 256>>>(wm, h, m, out);
}